// round 10
// baseline (speedup 1.0000x reference)
#include <cuda_runtime.h>

#define NQ      14
#define STATE   16384
#define BATCH   512
#define THREADS 512

__device__ __forceinline__ int swz(int i) { return i ^ ((i >> 5) & 31); }

__device__ __forceinline__ float2 cmul(float2 a, float2 b) {
    return make_float2(a.x * b.x - a.y * b.y, a.x * b.y + a.y * b.x);
}

// Complex in-register FWHT: NE elements, first NS stages (index bits in j).
template <int NE, int NS>
__device__ __forceinline__ void fwht_c(float2* v) {
#pragma unroll
    for (int s = 0; s < NS; s++) {
        const int h = 1 << s;
#pragma unroll
        for (int i = 0; i < NE / 2; i++) {
            const int k = i & (h - 1), g = (i >> s) << (s + 1);
            const int i0 = g + k, i1 = i0 + h;
            float2 a = v[i0], b = v[i1];
            v[i0] = make_float2(a.x + b.x, a.y + b.y);
            v[i1] = make_float2(a.x - b.x, a.y - b.y);
        }
    }
}

// Real in-register FWHT.
template <int NE, int NS>
__device__ __forceinline__ void fwht_r(float* v) {
#pragma unroll
    for (int s = 0; s < NS; s++) {
        const int h = 1 << s;
#pragma unroll
        for (int i = 0; i < NE / 2; i++) {
            const int k = i & (h - 1), g = (i >> s) << (s + 1);
            const int i0 = g + k, i1 = i0 + h;
            float a = v[i0], b = v[i1];
            v[i0] = a + b;
            v[i1] = a - b;
        }
    }
}

// Shuffle butterflies over lane bits 0..4 (5 stages), complex.
// v' = partner + s*v with s = -1 on the high lane: one FMA per component.
__device__ __forceinline__ void fwht_shfl_c(float2* v, int lane) {
#pragma unroll
    for (int h = 1; h <= 16; h <<= 1) {
        const float s = (lane & h) ? -1.f : 1.f;
#pragma unroll
        for (int j = 0; j < 32; j++) {
            const float ox = __shfl_xor_sync(0xFFFFFFFFu, v[j].x, h);
            const float oy = __shfl_xor_sync(0xFFFFFFFFu, v[j].y, h);
            v[j].x = fmaf(s, v[j].x, ox);
            v[j].y = fmaf(s, v[j].y, oy);
        }
    }
}

// Shuffle butterflies over lane bits 0..4, real.
__device__ __forceinline__ void fwht_shfl_r(float* r, int lane) {
#pragma unroll
    for (int h = 1; h <= 16; h <<= 1) {
        const float s = (lane & h) ? -1.f : 1.f;
#pragma unroll
        for (int j = 0; j < 32; j++) {
            const float o = __shfl_xor_sync(0xFFFFFFFFu, r[j], h);
            r[j] = fmaf(s, r[j], o);
        }
    }
}

// SMEM layout (float2 units): [0, STATE) data, fac(16), tabL(132 pad), tabH(128)
#define SM_FAC   (STATE)
#define SM_TABL  (STATE + 16)
#define SM_TABH  (STATE + 16 + 132)
#define SM_TOTAL (STATE + 16 + 132 + 128)

__global__ __launch_bounds__(THREADS, 1)
void rx_fused(const float* __restrict__ pr, const float* __restrict__ pim,
              const float* __restrict__ th, float* __restrict__ out,
              long long ocap) {
    extern __shared__ float2 sm[];
    float*  smf  = (float*)sm;
    float2* fac  = sm + SM_FAC;
    float2* tabL = sm + SM_TABL;   // entry m at [m + (m>>5)]
    float2* tabH = sm + SM_TABH;

    const int b    = blockIdx.x;
    const int t    = threadIdx.x;
    const int lane = t & 31;
    const int w    = t >> 5;

    if (t < NQ) {
        float s, c;
        __sincosf(-0.5f * th[b * NQ + t], &s, &c);
        fac[13 - t] = make_float2(c, s);   // bit p carries theta[13-p]
    }

    // ===== Pass A: FWHT1 bits {9..13 reg} + {0..4 shfl}; store complex smem.
    float2 v[32];
    {
        const float* prb = pr  + (size_t)b * STATE;
        const float* pib = pim + (size_t)b * STATE;
#pragma unroll
        for (int j = 0; j < 32; j++) {
            v[j].x = prb[t + 512 * j];
            v[j].y = pib[t + 512 * j];
        }
    }
    __syncthreads();   // fac visible

    // Kronecker half-tables (overlaps with butterfly compute below).
    if (t < 256) {
        const int m    = t & 127;
        const int base = (t < 128) ? 0 : 7;
        float2 e = (t < 128) ? make_float2(0x1p-14f, 0.f) : make_float2(1.f, 0.f);
#pragma unroll
        for (int k = 0; k < 7; k++)
            if ((m >> k) & 1) e = cmul(e, fac[base + k]);
        if (t < 128) tabL[m + (m >> 5)] = e;
        else         tabH[m]            = e;
    }

    fwht_c<32, 5>(v);          // bits 9..13
    fwht_shfl_c(v, lane);      // bits 0..4
#pragma unroll
    for (int j = 0; j < 32; j++) sm[swz(t + 512 * j)] = v[j];
    __syncthreads();

    // ===== Pass B: idx = w*1024 + j*32 + lane.
    // FWHT1 bits 5..8 (complex reg) -> diag -> REAL ->
    // FWHT2 bits {5..9 reg} + {0..4 shfl}; store real smem.
    float r[32];
    {
        const int base = w * 1024 + lane;
#pragma unroll
        for (int j = 0; j < 32; j++) v[j] = sm[swz(base + 32 * j)];
        fwht_c<32, 4>(v);      // bits 5..8 (j bits 0..3)

        // ev = tabH[idx>>7] * tabL[idx&127]; hi = (w<<3)|(j>>2), lo m = (j&3)*32+lane
#pragma unroll
        for (int j = 0; j < 32; j++) {
            const float2 e = cmul(tabH[(w << 3) | (j >> 2)],
                                  tabL[(j & 3) * 33 + lane]);
            r[j] = v[j].x * e.x - v[j].y * e.y;   // Re(ev * w)
        }

        fwht_r<32, 5>(r);      // bits 5..9 (all 5 j bits)
        fwht_shfl_r(r, lane);  // bits 0..4
        __syncthreads();       // all complex reads done before real alias writes
#pragma unroll
        for (int j = 0; j < 32; j++) smf[swz(base + 32 * j)] = r[j];
    }
    __syncthreads();

    // ===== Pass C: FWHT2 bits 10..13 (two real 16-point transforms); write out.
    {
        float* ob = out + (size_t)b * STATE;
        float q[32];
#pragma unroll
        for (int j = 0; j < 16; j++) {
            q[j]      = smf[swz(j * 1024 + t)];
            q[16 + j] = smf[swz(j * 1024 + t + 512)];
        }
        fwht_r<16, 4>(q);
        fwht_r<16, 4>(q + 16);
        const long long rb = (long long)b * STATE;
#pragma unroll
        for (int j = 0; j < 16; j++) {
            if (rb + j * 1024 + t       < ocap) ob[j * 1024 + t]       = q[j];
            if (rb + j * 1024 + t + 512 < ocap) ob[j * 1024 + t + 512] = q[16 + j];
        }
    }
}

extern "C" void kernel_launch(void* const* d_in, const int* in_sizes, int n_in,
                              void* d_out, int out_size) {
    // Contract (established R8): fp32 planar inputs; output = fp32 REAL part.
    // Ratio binding (order/extras robust): S_phi = S_th * 8192/7, occurring twice.
    int ia = -1, ib = -1, ith = -1;
    for (int k = 0; k < n_in && ith < 0; k++) {
        const long long st = in_sizes[k];
        if (st <= 0 || (st * 8192) % 7) continue;
        const long long sp = st * 8192 / 7;
        int a = -1, bb = -1;
        for (int j = 0; j < n_in; j++) {
            if (j == k) continue;
            if ((long long)in_sizes[j] == sp) { if (a < 0) a = j; else if (bb < 0) bb = j; }
        }
        if (a >= 0 && bb >= 0) { ith = k; ia = a; ib = bb; }
    }
    if (ith < 0) { if (n_in < 3) return; ia = 0; ib = 1; ith = 2; }

    const size_t smem = SM_TOTAL * sizeof(float2);   // 133,280 B
    if (cudaFuncSetAttribute(rx_fused,
            cudaFuncAttributeMaxDynamicSharedMemorySize, (int)smem) != cudaSuccess)
        return;
    rx_fused<<<BATCH, THREADS, smem>>>(
        (const float*)d_in[ia], (const float*)d_in[ib], (const float*)d_in[ith],
        (float*)d_out, (long long)out_size);
}

// round 11
// speedup vs baseline: 1.2065x; 1.2065x over previous
#include <cuda_runtime.h>

#define NQ      14
#define STATE   16384
#define BATCH   512
#define THREADS 512

typedef unsigned long long ull;

__device__ __forceinline__ int swz(int i) { return i ^ ((i >> 5) & 31); }

__device__ __forceinline__ float2 cmul(float2 a, float2 b) {
    return make_float2(a.x * b.x - a.y * b.y, a.x * b.y + a.y * b.x);
}

// ---- packed f32x2 helpers (Blackwell: FADD2/FFMA2 only reachable via PTX) ----
__device__ __forceinline__ ull pk(float x, float y) {
    ull r; asm("mov.b64 %0, {%1, %2};" : "=l"(r) : "f"(x), "f"(y)); return r;
}
__device__ __forceinline__ void upk(ull p, float& x, float& y) {
    asm("mov.b64 {%0, %1}, %2;" : "=f"(x), "=f"(y) : "l"(p));
}
__device__ __forceinline__ ull addx2(ull a, ull b) {
    ull r; asm("add.rn.f32x2 %0, %1, %2;" : "=l"(r) : "l"(a), "l"(b)); return r;
}
__device__ __forceinline__ ull subx2(ull a, ull b) {
    ull r; asm("sub.rn.f32x2 %0, %1, %2;" : "=l"(r) : "l"(a), "l"(b)); return r;
}

// Packed FWHT butterflies (each ull = 2 independent lanes): NE elems, NS stages.
template <int NE, int NS>
__device__ __forceinline__ void fwht_p(ull* v) {
#pragma unroll
    for (int s = 0; s < NS; s++) {
        const int h = 1 << s;
#pragma unroll
        for (int i = 0; i < NE / 2; i++) {
            const int k = i & (h - 1), g = (i >> s) << (s + 1);
            const int i0 = g + k, i1 = i0 + h;
            ull a = v[i0], b = v[i1];
            v[i0] = addx2(a, b);
            v[i1] = subx2(a, b);
        }
    }
}

// Real 32-elem FWHT, 5 stages, packed over independent pairs (k, k+16):
// stages h=1..8 packed; final h=16 stage = within-pack butterfly.
__device__ __forceinline__ void fwht_r32_packed(ull* p /*16*/) {
    fwht_p<16, 4>(p);                       // h = 1,2,4,8 on both halves
#pragma unroll
    for (int k = 0; k < 16; k++) {          // h = 16: (lo,hi) -> (lo+hi, lo-hi)
        float x, y; upk(p[k], x, y);
        p[k] = pk(x + y, x - y);
    }
}

// SMEM layout (float2/ull units): [0,STATE) data, fac(16), tabL(132 pad), tabH(128)
#define SM_FAC   (STATE)
#define SM_TABL  (STATE + 16)
#define SM_TABH  (STATE + 16 + 132)
#define SM_TOTAL (STATE + 16 + 132 + 128)

__global__ __launch_bounds__(THREADS, 1)
void rx_fused(const float* __restrict__ pr, const float* __restrict__ pim,
              const float* __restrict__ th, float* __restrict__ out,
              long long ocap) {
    extern __shared__ ull smu[];            // data region as packed complex
    float*  smf  = (float*)smu;             // real-phase alias
    float2* fac  = (float2*)(smu + SM_FAC);
    float2* tabL = (float2*)(smu + SM_TABL);   // entry m at [m + (m>>5)]
    float2* tabH = (float2*)(smu + SM_TABH);

    const int b    = blockIdx.x;
    const int t    = threadIdx.x;
    const int lane = t & 31;
    const int w    = t >> 5;
    (void)lane; (void)w;

    if (t < NQ) {
        float s, c;
        __sincosf(-0.5f * th[b * NQ + t], &s, &c);
        fac[13 - t] = make_float2(c, s);    // bit p carries theta[13-p]
    }

    // ===== Pass A: FWHT1 bits 9..13 (packed complex); store smem.
    ull v[32];
    {
        const float* prb = pr  + (size_t)b * STATE;
        const float* pib = pim + (size_t)b * STATE;
#pragma unroll
        for (int j = 0; j < 32; j++)
            v[j] = pk(prb[t + 512 * j], pib[t + 512 * j]);
    }
    __syncthreads();                         // fac visible

    // Kronecker half-tables: ev[s] = tabH[s>>7] * tabL[s&127]; tabL has 2^-14.
    if (t < 256) {
        const int m    = t & 127;
        const int base = (t < 128) ? 0 : 7;
        float2 e = (t < 128) ? make_float2(0x1p-14f, 0.f) : make_float2(1.f, 0.f);
#pragma unroll
        for (int k = 0; k < 7; k++)
            if ((m >> k) & 1) e = cmul(e, fac[base + k]);
        if (t < 128) tabL[m + (m >> 5)] = e;
        else         tabH[m]            = e;
    }

    fwht_p<32, 5>(v);
#pragma unroll
    for (int j = 0; j < 32; j++) smu[swz(t + 512 * j)] = v[j];
    __syncthreads();

    // ===== Pass B: bits 4..8 (packed complex).
    {
        const int base = (t >> 4) * 512 + (t & 15);
#pragma unroll
        for (int j = 0; j < 32; j++) v[j] = smu[swz(base + 16 * j)];
        fwht_p<32, 5>(v);
#pragma unroll
        for (int j = 0; j < 32; j++) smu[swz(base + 16 * j)] = v[j];
    }
    __syncthreads();

    // ===== Pass C: FWHT1 bits 0..3 (packed complex), diag -> REAL,
    //               FWHT2 bits 0..4 (packed real); store real floats.
    {
        const int base = t * 32;
#pragma unroll
        for (int j = 0; j < 32; j++) v[j] = smu[swz(base + j)];
        fwht_p<32, 4>(v);                    // bits 0..3

        const float2 hv   = tabH[t >> 2];
        const int   lbase = (t & 3) * 33;    // 32 + pad(m>>5)
        float r[32];
#pragma unroll
        for (int j = 0; j < 32; j++) {
            const float2 e = cmul(hv, tabL[lbase + j]);
            float x, y; upk(v[j], x, y);
            r[j] = fmaf(x, e.x, -(y * e.y)); // Re(ev * w)
        }

        ull p[16];
#pragma unroll
        for (int k = 0; k < 16; k++) p[k] = pk(r[k], r[k + 16]);
        fwht_r32_packed(p);                  // FWHT2 bits 0..4
        __syncthreads();                     // complex reads done before alias
#pragma unroll
        for (int k = 0; k < 16; k++) {
            float x, y; upk(p[k], x, y);
            smf[swz(base + k)]      = x;
            smf[swz(base + k + 16)] = y;
        }
    }
    __syncthreads();

    // ===== Pass D: FWHT2 bits 5..9 (packed real).
    {
        const int base = (t >> 5) * 1024 + (t & 31);
        ull p[16];
#pragma unroll
        for (int k = 0; k < 16; k++)
            p[k] = pk(smf[swz(base + 32 * k)], smf[swz(base + 32 * (k + 16))]);
        fwht_r32_packed(p);
#pragma unroll
        for (int k = 0; k < 16; k++) {
            float x, y; upk(p[k], x, y);
            smf[swz(base + 32 * k)]        = x;
            smf[swz(base + 32 * (k + 16))] = y;
        }
    }
    __syncthreads();

    // ===== Pass E: FWHT2 bits 10..13 — two independent 16-pt transforms,
    //               packed across them; write real plane.
    {
        float* ob = out + (size_t)b * STATE;
        ull p[16];
#pragma unroll
        for (int j = 0; j < 16; j++)
            p[j] = pk(smf[swz(j * 1024 + t)], smf[swz(j * 1024 + t + 512)]);
        fwht_p<16, 4>(p);                    // both transforms at once
        const long long rb = (long long)b * STATE;
#pragma unroll
        for (int j = 0; j < 16; j++) {
            float x, y; upk(p[j], x, y);
            if (rb + j * 1024 + t       < ocap) ob[j * 1024 + t]       = x;
            if (rb + j * 1024 + t + 512 < ocap) ob[j * 1024 + t + 512] = y;
        }
    }
}

extern "C" void kernel_launch(void* const* d_in, const int* in_sizes, int n_in,
                              void* d_out, int out_size) {
    // Contract (established R8): fp32 planar inputs; output = fp32 REAL part.
    int ia = -1, ib = -1, ith = -1;
    for (int k = 0; k < n_in && ith < 0; k++) {
        const long long st = in_sizes[k];
        if (st <= 0 || (st * 8192) % 7) continue;
        const long long sp = st * 8192 / 7;
        int a = -1, bb = -1;
        for (int j = 0; j < n_in; j++) {
            if (j == k) continue;
            if ((long long)in_sizes[j] == sp) { if (a < 0) a = j; else if (bb < 0) bb = j; }
        }
        if (a >= 0 && bb >= 0) { ith = k; ia = a; ib = bb; }
    }
    if (ith < 0) { if (n_in < 3) return; ia = 0; ib = 1; ith = 2; }

    const size_t smem = SM_TOTAL * sizeof(ull);   // 133,280 B
    if (cudaFuncSetAttribute(rx_fused,
            cudaFuncAttributeMaxDynamicSharedMemorySize, (int)smem) != cudaSuccess)
        return;
    rx_fused<<<BATCH, THREADS, smem>>>(
        (const float*)d_in[ia], (const float*)d_in[ib], (const float*)d_in[ith],
        (float*)d_out, (long long)out_size);
}